// round 5
// baseline (speedup 1.0000x reference)
#include <cuda_runtime.h>
#include <cstdint>

#define BB 32
#define TT 2048
#define CC 1152
#define OO 29
#define NCHUNK 16
#define NBLK (BB * NCHUNK)    // 512 blocks
#define TROWS (TT / NCHUNK)   // 128 t-rows per chunk
#define C4 (CC / 4)           // 288 float4 per row
#define ZP_STRIDE 32          // padded per-(b,chunk) output row

// Per-(b,chunk) projected partials. Fully overwritten every launch before the
// finisher reads them -> deterministic under graph replay.
__device__ float    g_zp[NBLK * ZP_STRIDE];
// Block-completion counter; the finishing block resets it to 0 so every graph
// replay starts from the same state.
__device__ unsigned g_count;

// ---------------------------------------------------------------------------
// Single fused kernel, 512 blocks x 288 threads:
//   (a) stream x with __ldcs (evict-first: read-once data must not thrash L2)
//       and reduce 128 t-rows. 288 x 16B = 4608 B = exactly one x row ->
//       perfectly coalesced. Unroll 8 -> 8 outstanding 16B loads/thread;
//       512 blocks keep 3-4 CTAs (27-36 warps) resident per SM -> the
//       concurrency regime that measured 6.4 TB/s in round 2.
//   (b) project the chunk's column-sum vector onto the 29 W rows (W stays
//       L2-hot because the x stream bypasses allocation).
//   (c) last block collapses chunk partials, adds T*bias, divides by length.
// ---------------------------------------------------------------------------
__global__ __launch_bounds__(C4, 3) void fused_kernel(const float* __restrict__ x,
                                                      const int*   __restrict__ length,
                                                      const float* __restrict__ W,
                                                      const float* __restrict__ bias,
                                                      float*       __restrict__ out) {
    __shared__ float s[CC];
    __shared__ bool  is_last;

    const int blk   = blockIdx.x;
    const int b     = blk / NCHUNK;
    const int chunk = blk % NCHUNK;
    const int tid   = threadIdx.x;

    // ---- (a) T-reduction mainloop ----
    const float4* xp = reinterpret_cast<const float4*>(x)
                     + ((size_t)b * TT + (size_t)chunk * TROWS) * C4 + tid;

    float4 acc = make_float4(0.f, 0.f, 0.f, 0.f);

    #pragma unroll 1
    for (int t = 0; t < TROWS; t += 8) {
        float4 v0 = __ldcs(&xp[(size_t)(t + 0) * C4]);
        float4 v1 = __ldcs(&xp[(size_t)(t + 1) * C4]);
        float4 v2 = __ldcs(&xp[(size_t)(t + 2) * C4]);
        float4 v3 = __ldcs(&xp[(size_t)(t + 3) * C4]);
        float4 v4 = __ldcs(&xp[(size_t)(t + 4) * C4]);
        float4 v5 = __ldcs(&xp[(size_t)(t + 5) * C4]);
        float4 v6 = __ldcs(&xp[(size_t)(t + 6) * C4]);
        float4 v7 = __ldcs(&xp[(size_t)(t + 7) * C4]);
        acc.x += ((v0.x + v1.x) + (v2.x + v3.x)) + ((v4.x + v5.x) + (v6.x + v7.x));
        acc.y += ((v0.y + v1.y) + (v2.y + v3.y)) + ((v4.y + v5.y) + (v6.y + v7.y));
        acc.z += ((v0.z + v1.z) + (v2.z + v3.z)) + ((v4.z + v5.z) + (v6.z + v7.z));
        acc.w += ((v0.w + v1.w) + (v2.w + v3.w)) + ((v4.w + v5.w) + (v6.w + v7.w));
    }

    reinterpret_cast<float4*>(s)[tid] = acc;
    __syncthreads();

    // ---- (b) projection epilogue: 9 warps round-robin the 29 outputs ----
    // val[c] = s[c]/64 - 2*TROWS, folded into the dot. float4 loads: 9 iters.
    const int warp = tid >> 5;
    const int lane = tid & 31;
    const float inv64 = 1.0f / 64.0f;
    const float shift = 2.0f * (float)TROWS;   // 256

    const float4* s4 = reinterpret_cast<const float4*>(s);

    for (int o = warp; o < OO; o += 9) {
        const float4* wr4 = reinterpret_cast<const float4*>(W + (size_t)o * CC);
        float dot = 0.f;
        #pragma unroll
        for (int k = 0; k < C4 / 32; k++) {          // 9 iterations
            int idx = lane + k * 32;
            float4 w = wr4[idx];
            float4 v = s4[idx];
            dot = fmaf(fmaf(v.x, inv64, -shift), w.x, dot);
            dot = fmaf(fmaf(v.y, inv64, -shift), w.y, dot);
            dot = fmaf(fmaf(v.z, inv64, -shift), w.z, dot);
            dot = fmaf(fmaf(v.w, inv64, -shift), w.w, dot);
        }
        #pragma unroll
        for (int off = 16; off; off >>= 1)
            dot += __shfl_down_sync(0xffffffffu, dot, off);
        if (lane == 0)
            g_zp[(size_t)blk * ZP_STRIDE + o] = dot;
    }

    // ---- (c) last-block finish ----
    __syncthreads();                    // all zp stores for this block issued
    if (tid == 0) {
        __threadfence();                // release: publish zp before counting
        unsigned old = atomicAdd(&g_count, 1u);
        is_last = (old == NBLK - 1);
    }
    __syncthreads();

    if (is_last) {
        __threadfence();                // acquire: see all blocks' zp
        for (int idx = tid; idx < BB * OO; idx += C4) {
            int bb = idx / OO;
            int oo = idx % OO;
            float z = 0.f;
            #pragma unroll
            for (int ch = 0; ch < NCHUNK; ch++)
                z += g_zp[(size_t)(bb * NCHUNK + ch) * ZP_STRIDE + oo];
            z += (float)TT * bias[oo];
            out[(size_t)bb * OO + oo] = z / (float)length[bb];
        }
        if (tid == 0) g_count = 0u;     // reset for next graph replay
    }
}

// ---------------------------------------------------------------------------
// Inputs (metadata order): x f32 [B,T,C], length i32 [B], W f32 [O,C], b f32 [O]
// Output: f32 [B,O]
// NOTE: length is int32 on device (JAX downcasts int64 with x64 off).
// ---------------------------------------------------------------------------
extern "C" void kernel_launch(void* const* d_in, const int* in_sizes, int n_in,
                              void* d_out, int out_size) {
    (void)in_sizes; (void)n_in; (void)out_size;
    const float* x      = (const float*)d_in[0];
    const int*   length = (const int*)d_in[1];
    const float* W      = (const float*)d_in[2];
    const float* bias   = (const float*)d_in[3];
    float*       out    = (float*)d_out;

    fused_kernel<<<NBLK, C4>>>(x, length, W, bias, out);
}

// round 8
// speedup vs baseline: 1.0976x; 1.0976x over previous
#include <cuda_runtime.h>
#include <cstdint>

#define BB 32
#define TT 2048
#define CC 1152
#define OO 29
#define NCHUNK 16
#define NBLK (BB * NCHUNK)    // 512 blocks
#define TROWS (TT / NCHUNK)   // 128 t-rows per chunk
#define C4 (CC / 4)           // 288 float4 per row
#define ZP_STRIDE 32          // padded per-(b,chunk) output row

// Per-(b,chunk) projected partials. Fully overwritten every launch before the
// finisher reads them -> deterministic under graph replay.
__device__ float    g_zp[NBLK * ZP_STRIDE];
// Block-completion counter; the finishing block resets it to 0 so every graph
// replay starts from the same state.
__device__ unsigned g_count;

// ---------------------------------------------------------------------------
// Single fused kernel, 512 blocks x 288 threads.
//
// Occupancy is the binding constraint established by rounds 2-5:
//   round 2 (lean regs, all 512 CTAs resident, one wave)  -> 6.4 TB/s
//   round 5 (72 regs, 3-CTA cap, 444 resident + 68 tail)  -> 4.9 TB/s
// So: unroll 4 (fewer live regs), plain LDG (no ldcs), and a forced 4-CTA
// minimum -> 148*4 = 592 slots >= 512 blocks -> one flat wave.
//
//   (a) stream x, reduce 128 t-rows (288 x 16B = one 4608B row, coalesced)
//   (b) project chunk column sums onto the 29 W rows (float4, L2-resident W)
//   (c) last block collapses chunk partials, adds T*bias, divides by length
// ---------------------------------------------------------------------------
__global__ __launch_bounds__(C4, 4) void fused_kernel(const float* __restrict__ x,
                                                      const int*   __restrict__ length,
                                                      const float* __restrict__ W,
                                                      const float* __restrict__ bias,
                                                      float*       __restrict__ out) {
    __shared__ float s[CC];
    __shared__ bool  is_last;

    const int blk   = blockIdx.x;
    const int b     = blk / NCHUNK;
    const int chunk = blk % NCHUNK;
    const int tid   = threadIdx.x;

    // ---- (a) T-reduction mainloop (round-2 config) ----
    const float4* xp = reinterpret_cast<const float4*>(x)
                     + ((size_t)b * TT + (size_t)chunk * TROWS) * C4 + tid;

    float4 acc = make_float4(0.f, 0.f, 0.f, 0.f);

    #pragma unroll 1
    for (int t = 0; t < TROWS; t += 4) {
        float4 v0 = xp[(size_t)(t + 0) * C4];
        float4 v1 = xp[(size_t)(t + 1) * C4];
        float4 v2 = xp[(size_t)(t + 2) * C4];
        float4 v3 = xp[(size_t)(t + 3) * C4];
        acc.x += (v0.x + v1.x) + (v2.x + v3.x);
        acc.y += (v0.y + v1.y) + (v2.y + v3.y);
        acc.z += (v0.z + v1.z) + (v2.z + v3.z);
        acc.w += (v0.w + v1.w) + (v2.w + v3.w);
    }

    reinterpret_cast<float4*>(s)[tid] = acc;
    __syncthreads();

    // ---- (b) projection epilogue: 9 warps round-robin the 29 outputs ----
    // val[c] = s[c]/64 - 2*TROWS, folded into the dot. float4 loads: 9 iters.
    const int warp = tid >> 5;
    const int lane = tid & 31;
    const float inv64 = 1.0f / 64.0f;
    const float shift = 2.0f * (float)TROWS;   // 256

    const float4* s4 = reinterpret_cast<const float4*>(s);

    for (int o = warp; o < OO; o += 9) {
        const float4* wr4 = reinterpret_cast<const float4*>(W + (size_t)o * CC);
        float dot = 0.f;
        #pragma unroll
        for (int k = 0; k < C4 / 32; k++) {          // 9 iterations
            int idx = lane + k * 32;
            float4 w = wr4[idx];
            float4 v = s4[idx];
            dot = fmaf(fmaf(v.x, inv64, -shift), w.x, dot);
            dot = fmaf(fmaf(v.y, inv64, -shift), w.y, dot);
            dot = fmaf(fmaf(v.z, inv64, -shift), w.z, dot);
            dot = fmaf(fmaf(v.w, inv64, -shift), w.w, dot);
        }
        #pragma unroll
        for (int off = 16; off; off >>= 1)
            dot += __shfl_down_sync(0xffffffffu, dot, off);
        if (lane == 0)
            g_zp[(size_t)blk * ZP_STRIDE + o] = dot;
    }

    // ---- (c) last-block finish ----
    __syncthreads();                    // all zp stores for this block issued
    if (tid == 0) {
        __threadfence();                // release: publish zp before counting
        unsigned old = atomicAdd(&g_count, 1u);
        is_last = (old == NBLK - 1);
    }
    __syncthreads();

    if (is_last) {
        __threadfence();                // acquire: see all blocks' zp
        for (int idx = tid; idx < BB * OO; idx += C4) {
            int bb = idx / OO;
            int oo = idx % OO;
            float z = 0.f;
            #pragma unroll
            for (int ch = 0; ch < NCHUNK; ch++)
                z += g_zp[(size_t)(bb * NCHUNK + ch) * ZP_STRIDE + oo];
            z += (float)TT * bias[oo];
            out[(size_t)bb * OO + oo] = z / (float)length[bb];
        }
        if (tid == 0) g_count = 0u;     // reset for next graph replay
    }
}

// ---------------------------------------------------------------------------
// Inputs (metadata order): x f32 [B,T,C], length i32 [B], W f32 [O,C], b f32 [O]
// Output: f32 [B,O]
// NOTE: length is int32 on device (JAX downcasts int64 with x64 off).
// ---------------------------------------------------------------------------
extern "C" void kernel_launch(void* const* d_in, const int* in_sizes, int n_in,
                              void* d_out, int out_size) {
    (void)in_sizes; (void)n_in; (void)out_size;
    const float* x      = (const float*)d_in[0];
    const int*   length = (const int*)d_in[1];
    const float* W      = (const float*)d_in[2];
    const float* bias   = (const float*)d_in[3];
    float*       out    = (float*)d_out;

    fused_kernel<<<NBLK, C4>>>(x, length, W, bias, out);
}